// round 1
// baseline (speedup 1.0000x reference)
#include <cuda_runtime.h>
#include <math.h>

// Problem constants
#define IMG       320
#define CH        3
#define TILE      32
#define NTILES_X  10
#define NPIX      1024        // TILE*TILE
#define D         72          // 3 channels * 24 kept patch offsets
#define BN        128         // n-rows per CTA (== threads per CTA)
#define BM        64          // m-block staged in smem per step
#define KF_STRIDE 76          // padded row stride (floats), 16B-aligned, low-conflict

__global__ __launch_bounds__(BN, 4)
void nlm_kernel(const float* __restrict__ img, float* __restrict__ out)
{
    // Static shared: 12KB image + 4KB sq + 64*76*4 = 19KB kfeat  (~35.4KB < 48KB)
    __shared__ __align__(16) float timg[CH * NPIX];
    __shared__ float ssq[NPIX];
    __shared__ __align__(16) float kf[BM * KF_STRIDE];

    const int tile = blockIdx.y;                 // 0..99
    const int ti = tile / NTILES_X;
    const int tj = tile % NTILES_X;
    const int tid = threadIdx.x;

    // ---- load tile image [3][32][32] into smem ----
    const int gbase = (ti * TILE) * IMG + tj * TILE;
    for (int idx = tid; idx < CH * NPIX; idx += BN) {
        int ch  = idx >> 10;
        int pix = idx & (NPIX - 1);
        int r = pix >> 5, c = pix & 31;
        timg[idx] = img[ch * (IMG * IMG) + gbase + r * IMG + c];
    }
    __syncthreads();

    // ---- per-pixel squared feature norm (patch 5x5, edge-clamped, center excluded) ----
    for (int p = tid; p < NPIX; p += BN) {
        int r = p >> 5, c = p & 31;
        float s = 0.f;
        #pragma unroll
        for (int k = 0; k < 25; k++) {
            if (k == 12) continue;               // exclude center
            int di = k / 5 - 2, dj = k % 5 - 2;
            int rr = min(max(r + di, 0), 31);
            int cc = min(max(c + dj, 0), 31);
            int off = rr * 32 + cc;
            #pragma unroll
            for (int ch = 0; ch < CH; ch++) {
                float v = timg[ch * NPIX + off];
                s = fmaf(v, v, s);
            }
        }
        ssq[p] = s;
    }
    __syncthreads();

    // ---- this thread's pixel n and its 72 query features in registers ----
    const int n = blockIdx.x * BN + tid;         // 0..1023
    const int r = n >> 5, c = n & 31;
    float q[D];
    {
        #pragma unroll
        for (int k = 0; k < 25; k++) {
            if (k == 12) continue;
            int kk = (k < 12) ? k : k - 1;
            int di = k / 5 - 2, dj = k % 5 - 2;
            int rr = min(max(r + di, 0), 31);
            int cc = min(max(c + dj, 0), 31);
            int off = rr * 32 + cc;
            #pragma unroll
            for (int ch = 0; ch < CH; ch++)
                q[ch * 24 + kk] = timg[ch * NPIX + off];
        }
    }
    const float sqn = ssq[n];

    float o0 = 0.f, o1 = 0.f, o2 = 0.f, den = 0.f;

    // ---- stream over all m in blocks of BM ----
    for (int m0 = 0; m0 < NPIX; m0 += BM) {
        __syncthreads();                         // kf reuse barrier
        if (tid < BM) {
            int m  = m0 + tid;
            int mr = m >> 5, mc = m & 31;
            float* krow = &kf[tid * KF_STRIDE];
            #pragma unroll
            for (int k = 0; k < 25; k++) {
                if (k == 12) continue;
                int kk = (k < 12) ? k : k - 1;
                int di = k / 5 - 2, dj = k % 5 - 2;
                int rr = min(max(mr + di, 0), 31);
                int cc = min(max(mc + dj, 0), 31);
                int off = rr * 32 + cc;
                #pragma unroll
                for (int ch = 0; ch < CH; ch++)
                    krow[ch * 24 + kk] = timg[ch * NPIX + off];
            }
        }
        __syncthreads();

        for (int mi = 0; mi < BM; mi++) {
            const int m = m0 + mi;
            const float4* krow = (const float4*)&kf[mi * KF_STRIDE];
            float d0 = 0.f, d1 = 0.f, d2 = 0.f, d3 = 0.f;
            #pragma unroll
            for (int k = 0; k < D / 4; k++) {
                float4 kv = krow[k];
                d0 = fmaf(q[4 * k + 0], kv.x, d0);
                d1 = fmaf(q[4 * k + 1], kv.y, d1);
                d2 = fmaf(q[4 * k + 2], kv.z, d2);
                d3 = fmaf(q[4 * k + 3], kv.w, d3);
            }
            float dot  = (d0 + d1) + (d2 + d3);
            float dd   = sqn + ssq[m] - 2.f * dot;
            float dist = sqrtf(fmaxf(dd, 0.f));
            float w    = __expf(-dist);
            if (m == n) w = 0.f;                 // diag -> zero weight
            den += w;
            o0 = fmaf(w, timg[m],            o0);
            o1 = fmaf(w, timg[NPIX + m],     o1);
            o2 = fmaf(w, timg[2 * NPIX + m], o2);
        }
    }

    const float inv = 1.f / den;
    const int obase = gbase + r * IMG + c;
    out[obase]                 = o0 * inv;
    out[IMG * IMG + obase]     = o1 * inv;
    out[2 * IMG * IMG + obase] = o2 * inv;
}

extern "C" void kernel_launch(void* const* d_in, const int* in_sizes, int n_in,
                              void* d_out, int out_size)
{
    (void)in_sizes; (void)n_in; (void)out_size;
    const float* img = (const float*)d_in[0];
    float* out = (float*)d_out;
    dim3 grid(NPIX / BN, 100);   // (8 n-blocks, 100 tiles)
    nlm_kernel<<<grid, BN>>>(img, out);
}

// round 2
// speedup vs baseline: 1.1043x; 1.1043x over previous
#include <cuda_runtime.h>
#include <math.h>

// Problem constants
#define IMG       320
#define CH        3
#define TILE      32
#define NTILES_X  10
#define NPIX      1024        // TILE*TILE
#define D         72          // 3 channels * 24 kept patch offsets
#define BN        128         // n-rows per CTA (== threads per CTA)
#define BM        64          // m-block staged in smem per step
#define KF_STRIDE 76          // padded row stride (floats), 16B-aligned

typedef unsigned long long ull;

// Packed fp32x2 ops (Blackwell FFMA2/FADD2 — PTX-only, not emitted from C++)
__device__ __forceinline__ ull fma2(ull a, ull b, ull c) {
    ull d; asm("fma.rn.f32x2 %0, %1, %2, %3;" : "=l"(d) : "l"(a), "l"(b), "l"(c));
    return d;
}
__device__ __forceinline__ ull add2(ull a, ull b) {
    ull d; asm("add.rn.f32x2 %0, %1, %2;" : "=l"(d) : "l"(a), "l"(b));
    return d;
}
__device__ __forceinline__ ull pack2(float lo, float hi) {
    ull d; asm("mov.b64 %0, {%1, %2};" : "=l"(d) : "f"(lo), "f"(hi));
    return d;
}
__device__ __forceinline__ float2 unpack2(ull v) {
    float lo, hi; asm("mov.b64 {%0, %1}, %2;" : "=f"(lo), "=f"(hi) : "l"(v));
    return make_float2(lo, hi);
}

__global__ __launch_bounds__(BN, 4)
void nlm_kernel(const float* __restrict__ img, float* __restrict__ out)
{
    // Static shared: 12KB image + 16KB aux4(I0,I1,I2,ssq) + 19KB kfeat = 47KB
    __shared__ __align__(16) float timg[CH * NPIX];
    __shared__ __align__(16) float4 aux4[NPIX];
    __shared__ __align__(16) float kf[BM * KF_STRIDE];

    const int tile = blockIdx.y;                 // 0..99
    const int ti = tile / NTILES_X;
    const int tj = tile % NTILES_X;
    const int tid = threadIdx.x;

    // ---- load tile image [3][32][32] into smem ----
    const int gbase = (ti * TILE) * IMG + tj * TILE;
    for (int idx = tid; idx < CH * NPIX; idx += BN) {
        int ch  = idx >> 10;
        int pix = idx & (NPIX - 1);
        int r = pix >> 5, c = pix & 31;
        timg[idx] = img[ch * (IMG * IMG) + gbase + r * IMG + c];
    }
    __syncthreads();

    // ---- per-pixel squared feature norm + fused (I0,I1,I2,ssq) vector ----
    for (int p = tid; p < NPIX; p += BN) {
        int r = p >> 5, c = p & 31;
        float s = 0.f;
        #pragma unroll
        for (int k = 0; k < 25; k++) {
            if (k == 12) continue;               // exclude center
            int di = k / 5 - 2, dj = k % 5 - 2;
            int rr = min(max(r + di, 0), 31);
            int cc = min(max(c + dj, 0), 31);
            int off = rr * 32 + cc;
            #pragma unroll
            for (int ch = 0; ch < CH; ch++) {
                float v = timg[ch * NPIX + off];
                s = fmaf(v, v, s);
            }
        }
        aux4[p] = make_float4(timg[p], timg[NPIX + p], timg[2 * NPIX + p], s);
    }
    __syncthreads();

    // ---- this thread's pixel n: 72 query features packed into 36 f32x2 regs ----
    const int n = blockIdx.x * BN + tid;         // 0..1023
    const int r = n >> 5, c = n & 31;
    float qf[D];
    {
        #pragma unroll
        for (int k = 0; k < 25; k++) {
            if (k == 12) continue;
            int kk = (k < 12) ? k : k - 1;
            int di = k / 5 - 2, dj = k % 5 - 2;
            int rr = min(max(r + di, 0), 31);
            int cc = min(max(c + dj, 0), 31);
            int off = rr * 32 + cc;
            #pragma unroll
            for (int ch = 0; ch < CH; ch++)
                qf[ch * 24 + kk] = timg[ch * NPIX + off];
        }
    }
    ull q2[D / 2];
    #pragma unroll
    for (int i = 0; i < D / 2; i++)
        q2[i] = pack2(qf[2 * i], qf[2 * i + 1]);
    const float sqn = aux4[n].w;

    float o0 = 0.f, o1 = 0.f, o2 = 0.f, den = 0.f;

    // ---- stream over all m in blocks of BM ----
    for (int m0 = 0; m0 < NPIX; m0 += BM) {
        __syncthreads();                         // kf reuse barrier
        if (tid < BM) {
            int m  = m0 + tid;
            int mr = m >> 5, mc = m & 31;
            float* krow = &kf[tid * KF_STRIDE];
            #pragma unroll
            for (int k = 0; k < 25; k++) {
                if (k == 12) continue;
                int kk = (k < 12) ? k : k - 1;
                int di = k / 5 - 2, dj = k % 5 - 2;
                int rr = min(max(mr + di, 0), 31);
                int cc = min(max(mc + dj, 0), 31);
                int off = rr * 32 + cc;
                #pragma unroll
                for (int ch = 0; ch < CH; ch++)
                    krow[ch * 24 + kk] = timg[ch * NPIX + off];
            }
        }
        __syncthreads();

        #pragma unroll 2
        for (int mi = 0; mi < BM; mi++) {
            const int m = m0 + mi;
            const ulonglong2* krow = (const ulonglong2*)&kf[mi * KF_STRIDE];
            ull a0 = 0ull, a1 = 0ull, a2 = 0ull, a3 = 0ull;
            #pragma unroll
            for (int k = 0; k < D / 8; k++) {    // 9 iters, 4 FFMA2 each
                ulonglong2 kva = krow[2 * k];
                ulonglong2 kvb = krow[2 * k + 1];
                a0 = fma2(q2[4 * k + 0], kva.x, a0);
                a1 = fma2(q2[4 * k + 1], kva.y, a1);
                a2 = fma2(q2[4 * k + 2], kvb.x, a2);
                a3 = fma2(q2[4 * k + 3], kvb.y, a3);
            }
            ull s = add2(add2(a0, a1), add2(a2, a3));
            float2 sf = unpack2(s);
            float dot = sf.x + sf.y;

            float4 am = aux4[m];                 // (I0, I1, I2, ssq) in one LDS.128
            float dd   = fmaf(-2.f, dot, sqn + am.w);
            float dist = sqrtf(fmaxf(dd, 0.f));
            float w    = __expf(-dist);
            if (m == n) w = 0.f;                 // diag -> zero weight
            den += w;
            o0 = fmaf(w, am.x, o0);
            o1 = fmaf(w, am.y, o1);
            o2 = fmaf(w, am.z, o2);
        }
    }

    const float inv = 1.f / den;
    const int obase = gbase + r * IMG + c;
    out[obase]                 = o0 * inv;
    out[IMG * IMG + obase]     = o1 * inv;
    out[2 * IMG * IMG + obase] = o2 * inv;
}

extern "C" void kernel_launch(void* const* d_in, const int* in_sizes, int n_in,
                              void* d_out, int out_size)
{
    (void)in_sizes; (void)n_in; (void)out_size;
    const float* img = (const float*)d_in[0];
    float* out = (float*)d_out;
    dim3 grid(NPIX / BN, 100);   // (8 n-blocks, 100 tiles)
    nlm_kernel<<<grid, BN>>>(img, out);
}

// round 4
// speedup vs baseline: 2.8430x; 2.5744x over previous
#include <cuda_runtime.h>
#include <cuda_fp16.h>
#include <stdint.h>
#include <math.h>

#define IMG   320
#define NPIX  1024
#define YROWB 176           // bytes per Y row: 88 halfs (80 used + pad), 16B-aligned

// shared layout (bytes)
#define SM_TIMG 0
#define SM_AUX  12288       // float4[1024]  (I0,I1,I2,ssq)
#define SM_Y    28672       // half[1024][88]
#define SM_RED  208896      // float4[256]
#define SMEM_TOTAL 212992

__device__ __forceinline__ uint32_t smem_u32(const void* p) {
    uint32_t a;
    asm("{ .reg .u64 t; cvta.to.shared.u64 t, %1; cvt.u32.u64 %0, t; }" : "=r"(a) : "l"(p));
    return a;
}
#define LDSM4(r, addr) \
    asm volatile("ldmatrix.sync.aligned.m8n8.x4.shared.b16 {%0,%1,%2,%3}, [%4];" \
        : "=r"((r)[0]), "=r"((r)[1]), "=r"((r)[2]), "=r"((r)[3]) : "r"(addr))
#define MMA16816(c, a, b0, b1) \
    asm volatile("mma.sync.aligned.m16n8k16.row.col.f32.f16.f16.f32 " \
        "{%0,%1,%2,%3}, {%4,%5,%6,%7}, {%8,%9}, {%0,%1,%2,%3};" \
        : "+f"((c)[0]), "+f"((c)[1]), "+f"((c)[2]), "+f"((c)[3]) \
        : "r"((a)[0]), "r"((a)[1]), "r"((a)[2]), "r"((a)[3]), "r"(b0), "r"(b1))

__global__ __launch_bounds__(256, 1)
void nlm_hmma_kernel(const float* __restrict__ img, float* __restrict__ out)
{
    extern __shared__ char sm[];
    float*  timg = (float*)(sm + SM_TIMG);
    float4* aux  = (float4*)(sm + SM_AUX);
    char*   Yb   = sm + SM_Y;
    float4* red  = (float4*)(sm + SM_RED);

    const int bid  = blockIdx.x;
    const int tile = bid >> 3, nb = bid & 7;
    const int ti = tile / 10, tj = tile % 10;
    const int tid = threadIdx.x;
    const int gb = ti * 32 * IMG + tj * 32;

    // ---- tile image -> smem ----
    for (int i = tid; i < 3 * NPIX; i += 256) {
        int ch = i >> 10, pix = i & 1023;
        timg[i] = img[ch * (IMG * IMG) + gb + (pix >> 5) * IMG + (pix & 31)];
    }
    __syncthreads();

    // ---- build fp16 feature rows Y[1024][80] + aux (I0,I1,I2, ssq of rounded) ----
    for (int p = tid; p < NPIX; p += 256) {
        int r = p >> 5, c = p & 31;
        __half hl[72];
        float sq = 0.f;
        #pragma unroll
        for (int k = 0; k < 25; k++) {
            if (k == 12) continue;
            int kk = (k < 12) ? k : k - 1;
            int rr = min(max(r + k / 5 - 2, 0), 31);
            int cc = min(max(c + k % 5 - 2, 0), 31);
            int off = rr * 32 + cc;
            #pragma unroll
            for (int ch = 0; ch < 3; ch++) {
                float x = timg[ch * NPIX + off];
                __half h = __float2half_rn(x);
                float xr = __half2float(h);
                sq = fmaf(xr, xr, sq);
                hl[ch * 24 + kk] = h;
            }
        }
        __half2* yrow = (__half2*)(Yb + p * YROWB);
        #pragma unroll
        for (int i = 0; i < 36; i++)
            yrow[i] = __halves2half2(hl[2 * i], hl[2 * i + 1]);
        #pragma unroll
        for (int i = 36; i < 44; i++)
            ((uint32_t*)yrow)[i] = 0u;        // zero pad cols 72..87
        aux[p] = make_float4(timg[p], timg[NPIX + p], timg[2 * NPIX + p], sq);
    }
    __syncthreads();

    // ---- warp/tile geometry ----
    const int wid = tid >> 5, lane = tid & 31;
    const int wn = wid >> 1;         // 0..3 : 32-row n sub-block
    const int wm2 = wid & 1;         // 0/1  : 64-col m half
    const int grb = nb * 128 + wn * 32;
    const uint32_t ybase = smem_u32(Yb);

    // ---- A fragments hoisted: 2 n16-tiles x 5 k16-steps ----
    uint32_t a[2][5][4];
    {
        int row = lane & 15;
        int cb  = (lane >> 4) << 4;
        #pragma unroll
        for (int nt = 0; nt < 2; nt++)
            #pragma unroll
            for (int ks = 0; ks < 5; ks++) {
                uint32_t ad = ybase + (uint32_t)(grb + nt * 16 + row) * YROWB + ks * 32 + cb;
                LDSM4(a[nt][ks], ad);
            }
    }

    // per-row squared norms (rows this thread owns in C frags)
    float sqn[2][2];
    #pragma unroll
    for (int nt = 0; nt < 2; nt++)
        #pragma unroll
        for (int h = 0; h < 2; h++)
            sqn[nt][h] = aux[grb + nt * 16 + h * 8 + (lane >> 2)].w;

    float den[2][2] = {}, ro0[2][2] = {}, ro1[2][2] = {}, ro2[2][2] = {};

    // ---- stream m in 128-blocks (each warp does its 64-col half) ----
    for (int mb = 0; mb < 8; mb++) {
        const int mbase = mb * 128 + wm2 * 64;
        float c[2][8][4];
        #pragma unroll
        for (int nt = 0; nt < 2; nt++)
            #pragma unroll
            for (int mt = 0; mt < 8; mt++)
                c[nt][mt][0] = c[nt][mt][1] = c[nt][mt][2] = c[nt][mt][3] = 0.f;

        #pragma unroll
        for (int ks = 0; ks < 5; ks++) {
            uint32_t b[16];
            #pragma unroll
            for (int bt = 0; bt < 4; bt++) {
                int row = mbase + bt * 16 + (lane & 7) + ((lane >> 4) << 3);
                int cb  = ks * 32 + (((lane >> 3) & 1) << 4);
                LDSM4(&b[bt * 4], ybase + (uint32_t)row * YROWB + cb);
            }
            #pragma unroll
            for (int nt = 0; nt < 2; nt++)
                #pragma unroll
                for (int mt = 0; mt < 8; mt++) {
                    int bi = (mt >> 1) * 4 + (mt & 1) * 2;
                    MMA16816(c[nt][mt], a[nt][ks], b[bi], b[bi + 1]);
                }
        }

        // ---- in-register epilogue ----
        #pragma unroll
        for (int mt = 0; mt < 8; mt++) {
            int c0 = mbase + mt * 8 + ((lane & 3) << 1);
            float4 aA = aux[c0], aB = aux[c0 + 1];
            #pragma unroll
            for (int nt = 0; nt < 2; nt++)
                #pragma unroll
                for (int h = 0; h < 2; h++) {
                    int gr = grb + nt * 16 + h * 8 + (lane >> 2);
                    float s = sqn[nt][h];
                    float d0 = fmaf(-2.f, c[nt][mt][h * 2 + 0], s + aA.w);
                    float d1 = fmaf(-2.f, c[nt][mt][h * 2 + 1], s + aB.w);
                    float w0 = __expf(-sqrtf(fmaxf(d0, 0.f)));
                    float w1 = __expf(-sqrtf(fmaxf(d1, 0.f)));
                    if (gr == c0)     w0 = 0.f;
                    if (gr == c0 + 1) w1 = 0.f;
                    den[nt][h] += w0 + w1;
                    ro0[nt][h] = fmaf(w0, aA.x, fmaf(w1, aB.x, ro0[nt][h]));
                    ro1[nt][h] = fmaf(w0, aA.y, fmaf(w1, aB.y, ro1[nt][h]));
                    ro2[nt][h] = fmaf(w0, aA.z, fmaf(w1, aB.z, ro2[nt][h]));
                }
        }
    }

    // ---- quad reduce (lanes sharing a row) then cross-warp via smem ----
    #pragma unroll
    for (int nt = 0; nt < 2; nt++)
        #pragma unroll
        for (int h = 0; h < 2; h++) {
            float d = den[nt][h], x = ro0[nt][h], y = ro1[nt][h], z = ro2[nt][h];
            #pragma unroll
            for (int off = 1; off <= 2; off <<= 1) {
                d += __shfl_xor_sync(0xFFFFFFFFu, d, off);
                x += __shfl_xor_sync(0xFFFFFFFFu, x, off);
                y += __shfl_xor_sync(0xFFFFFFFFu, y, off);
                z += __shfl_xor_sync(0xFFFFFFFFu, z, off);
            }
            if ((lane & 3) == 0) {
                int rl = wn * 32 + nt * 16 + h * 8 + (lane >> 2);
                red[wm2 * 128 + rl] = make_float4(x, y, z, d);
            }
        }
    __syncthreads();

    if (tid < 128) {
        float4 p0 = red[tid], p1 = red[128 + tid];
        float inv = 1.f / (p0.w + p1.w);
        int n = nb * 128 + tid;
        int gp = gb + (n >> 5) * IMG + (n & 31);
        out[gp]                 = (p0.x + p1.x) * inv;
        out[IMG * IMG + gp]     = (p0.y + p1.y) * inv;
        out[2 * IMG * IMG + gp] = (p0.z + p1.z) * inv;
    }
}

extern "C" void kernel_launch(void* const* d_in, const int* in_sizes, int n_in,
                              void* d_out, int out_size)
{
    (void)in_sizes; (void)n_in; (void)out_size;
    const float* img = (const float*)d_in[0];
    float* out = (float*)d_out;
    cudaFuncSetAttribute(nlm_hmma_kernel, cudaFuncAttributeMaxDynamicSharedMemorySize, SMEM_TOTAL);
    nlm_hmma_kernel<<<800, 256, SMEM_TOTAL>>>(img, out);
}

// round 5
// speedup vs baseline: 4.1394x; 1.4560x over previous
#include <cuda_runtime.h>
#include <cuda_fp16.h>
#include <stdint.h>
#include <math.h>

#define IMG   320
#define NPIX  1024
#define YROWB 144           // 72 halfs, 16B aligned; stride%128=16 -> conflict-free ldmatrix

// shared layout (bytes): red overlays timg (timg dead after Y build)
#define SM_TIMG 0           // 12288 B  (also red: float4[512] = 8192 B, after sync)
#define SM_AUX  12288       // float4[1024] (I0,I1,I2,ssq)
#define SM_Y    28672       // half[1024][72]
#define SMEM_TOTAL (28672 + NPIX * YROWB)   // 176128

__device__ __forceinline__ uint32_t smem_u32(const void* p) {
    uint32_t a;
    asm("{ .reg .u64 t; cvta.to.shared.u64 t, %1; cvt.u32.u64 %0, t; }" : "=r"(a) : "l"(p));
    return a;
}
#define LDSM4(r, addr) \
    asm volatile("ldmatrix.sync.aligned.m8n8.x4.shared.b16 {%0,%1,%2,%3}, [%4];" \
        : "=r"((r)[0]), "=r"((r)[1]), "=r"((r)[2]), "=r"((r)[3]) : "r"(addr))
#define LDSM2(r, addr) \
    asm volatile("ldmatrix.sync.aligned.m8n8.x2.shared.b16 {%0,%1}, [%2];" \
        : "=r"((r)[0]), "=r"((r)[1]) : "r"(addr))
#define MMA16816(c, a, b0, b1) \
    asm volatile("mma.sync.aligned.m16n8k16.row.col.f32.f16.f16.f32 " \
        "{%0,%1,%2,%3}, {%4,%5,%6,%7}, {%8,%9}, {%0,%1,%2,%3};" \
        : "+f"((c)[0]), "+f"((c)[1]), "+f"((c)[2]), "+f"((c)[3]) \
        : "r"((a)[0]), "r"((a)[1]), "r"((a)[2]), "r"((a)[3]), "r"(b0), "r"(b1))
#define MMA16808(c, a, b0) \
    asm volatile("mma.sync.aligned.m16n8k8.row.col.f32.f16.f16.f32 " \
        "{%0,%1,%2,%3}, {%4,%5}, {%6}, {%0,%1,%2,%3};" \
        : "+f"((c)[0]), "+f"((c)[1]), "+f"((c)[2]), "+f"((c)[3]) \
        : "r"((a)[0]), "r"((a)[1]), "r"(b0))

__global__ __launch_bounds__(512, 1)
void nlm_hmma_kernel(const float* __restrict__ img, float* __restrict__ out)
{
    extern __shared__ char sm[];
    float*  timg = (float*)(sm + SM_TIMG);
    float4* red  = (float4*)(sm + SM_TIMG);      // overlays timg after build
    float4* aux  = (float4*)(sm + SM_AUX);
    char*   Yb   = sm + SM_Y;

    const int bid  = blockIdx.x;
    const int tile = bid >> 2, nb = bid & 3;     // 256 rows per CTA
    const int ti = tile / 10, tj = tile % 10;
    const int tid = threadIdx.x;
    const int gb = ti * 32 * IMG + tj * 32;

    // ---- tile image -> smem ----
    for (int i = tid; i < 3 * NPIX; i += 512) {
        int ch = i >> 10, pix = i & 1023;
        timg[i] = img[ch * (IMG * IMG) + gb + (pix >> 5) * IMG + (pix & 31)];
    }
    __syncthreads();

    // ---- build fp16 features Y[1024][72] + aux (I0,I1,I2, ssq of rounded) ----
    for (int p = tid; p < NPIX; p += 512) {
        int r = p >> 5, c = p & 31;
        __half hl[72];
        float sq = 0.f;
        #pragma unroll
        for (int k = 0; k < 25; k++) {
            if (k == 12) continue;
            int kk = (k < 12) ? k : k - 1;
            int rr = min(max(r + k / 5 - 2, 0), 31);
            int cc = min(max(c + k % 5 - 2, 0), 31);
            int off = rr * 32 + cc;
            #pragma unroll
            for (int ch = 0; ch < 3; ch++) {
                float x = timg[ch * NPIX + off];
                __half h = __float2half_rn(x);
                float xr = __half2float(h);
                sq = fmaf(xr, xr, sq);
                hl[ch * 24 + kk] = h;
            }
        }
        __half2* yrow = (__half2*)(Yb + p * YROWB);
        #pragma unroll
        for (int i = 0; i < 36; i++)
            yrow[i] = __halves2half2(hl[2 * i], hl[2 * i + 1]);
        aux[p] = make_float4(timg[p], timg[NPIX + p], timg[2 * NPIX + p], sq);
    }
    __syncthreads();

    // ---- warp geometry: 16 warps = 8 n-subblocks x 2 m-halves ----
    const int wid = tid >> 5, lane = tid & 31;
    const int wn = wid >> 1;         // 0..7 : 32-row n sub-block
    const int wm2 = wid & 1;         // 0/1  : 64-col m half
    const int grb = nb * 256 + wn * 32;
    const uint32_t ybase = smem_u32(Yb);

    // ---- A fragments hoisted: 2 n16-tiles x (4 k16 + 1 k8) ----
    uint32_t a[2][4][4], a8[2][2];
    {
        int row = lane & 15;
        int cb  = (lane >> 4) << 4;
        #pragma unroll
        for (int nt = 0; nt < 2; nt++) {
            #pragma unroll
            for (int ks = 0; ks < 4; ks++)
                LDSM4(a[nt][ks], ybase + (uint32_t)(grb + nt * 16 + row) * YROWB + ks * 32 + cb);
            LDSM2(a8[nt], ybase + (uint32_t)(grb + nt * 16 + row) * YROWB + 128);
        }
    }

    float sqn[2][2];
    #pragma unroll
    for (int nt = 0; nt < 2; nt++)
        #pragma unroll
        for (int h = 0; h < 2; h++)
            sqn[nt][h] = aux[grb + nt * 16 + h * 8 + (lane >> 2)].w;

    float den[2][2] = {}, ro0[2][2] = {}, ro1[2][2] = {}, ro2[2][2] = {};

    // ---- stream m: 8 blocks of 128; warp takes its 64-col half in 2 groups of 32 ----
    for (int mb = 0; mb < 8; mb++) {
        #pragma unroll
        for (int g = 0; g < 2; g++) {
            const int mgb = mb * 128 + wm2 * 64 + g * 32;
            float c[2][4][4];
            #pragma unroll
            for (int nt = 0; nt < 2; nt++)
                #pragma unroll
                for (int mt = 0; mt < 4; mt++)
                    c[nt][mt][0] = c[nt][mt][1] = c[nt][mt][2] = c[nt][mt][3] = 0.f;

            #pragma unroll
            for (int ks = 0; ks < 4; ks++) {
                uint32_t b[8];
                #pragma unroll
                for (int bt = 0; bt < 2; bt++) {
                    int row = mgb + bt * 16 + (lane & 7) + ((lane >> 4) << 3);
                    int cb  = ks * 32 + (((lane >> 3) & 1) << 4);
                    LDSM4(&b[bt * 4], ybase + (uint32_t)row * YROWB + cb);
                }
                #pragma unroll
                for (int nt = 0; nt < 2; nt++)
                    #pragma unroll
                    for (int mt = 0; mt < 4; mt++) {
                        int bi = (mt >> 1) * 4 + (mt & 1) * 2;
                        MMA16816(c[nt][mt], a[nt][ks], b[bi], b[bi + 1]);
                    }
            }
            {   // k8 tail (cols 64..71)
                uint32_t b8[4];
                int row = mgb + (lane >> 3) * 8 + (lane & 7);
                LDSM4(b8, ybase + (uint32_t)row * YROWB + 128);
                #pragma unroll
                for (int nt = 0; nt < 2; nt++)
                    #pragma unroll
                    for (int mt = 0; mt < 4; mt++)
                        MMA16808(c[nt][mt], a8[nt], b8[mt]);
            }

            // ---- fused epilogue on this 32-col group ----
            #pragma unroll
            for (int mt = 0; mt < 4; mt++) {
                int c0 = mgb + mt * 8 + ((lane & 3) << 1);
                float4 aA = aux[c0], aB = aux[c0 + 1];
                #pragma unroll
                for (int nt = 0; nt < 2; nt++)
                    #pragma unroll
                    for (int h = 0; h < 2; h++) {
                        int gr = grb + nt * 16 + h * 8 + (lane >> 2);
                        float s = sqn[nt][h];
                        float d0 = fmaf(-2.f, c[nt][mt][h * 2 + 0], s + aA.w);
                        float d1 = fmaf(-2.f, c[nt][mt][h * 2 + 1], s + aB.w);
                        float w0 = __expf(-sqrtf(fmaxf(d0, 0.f)));
                        float w1 = __expf(-sqrtf(fmaxf(d1, 0.f)));
                        if (gr == c0)     w0 = 0.f;
                        if (gr == c0 + 1) w1 = 0.f;
                        den[nt][h] += w0 + w1;
                        ro0[nt][h] = fmaf(w0, aA.x, fmaf(w1, aB.x, ro0[nt][h]));
                        ro1[nt][h] = fmaf(w0, aA.y, fmaf(w1, aB.y, ro1[nt][h]));
                        ro2[nt][h] = fmaf(w0, aA.z, fmaf(w1, aB.z, ro2[nt][h]));
                    }
            }
        }
    }

    __syncthreads();   // timg fully dead everywhere before red overlay is written

    // ---- quad reduce then cross-warp-half combine via smem ----
    #pragma unroll
    for (int nt = 0; nt < 2; nt++)
        #pragma unroll
        for (int h = 0; h < 2; h++) {
            float d = den[nt][h], x = ro0[nt][h], y = ro1[nt][h], z = ro2[nt][h];
            #pragma unroll
            for (int off = 1; off <= 2; off <<= 1) {
                d += __shfl_xor_sync(0xFFFFFFFFu, d, off);
                x += __shfl_xor_sync(0xFFFFFFFFu, x, off);
                y += __shfl_xor_sync(0xFFFFFFFFu, y, off);
                z += __shfl_xor_sync(0xFFFFFFFFu, z, off);
            }
            if ((lane & 3) == 0) {
                int rl = wn * 32 + nt * 16 + h * 8 + (lane >> 2);
                red[wm2 * 256 + rl] = make_float4(x, y, z, d);
            }
        }
    __syncthreads();

    if (tid < 256) {
        float4 p0 = red[tid], p1 = red[256 + tid];
        float inv = 1.f / (p0.w + p1.w);
        int n = nb * 256 + tid;
        int gp = gb + (n >> 5) * IMG + (n & 31);
        out[gp]                 = (p0.x + p1.x) * inv;
        out[IMG * IMG + gp]     = (p0.y + p1.y) * inv;
        out[2 * IMG * IMG + gp] = (p0.z + p1.z) * inv;
    }
}

extern "C" void kernel_launch(void* const* d_in, const int* in_sizes, int n_in,
                              void* d_out, int out_size)
{
    (void)in_sizes; (void)n_in; (void)out_size;
    const float* img = (const float*)d_in[0];
    float* out = (float*)d_out;
    cudaFuncSetAttribute(nlm_hmma_kernel, cudaFuncAttributeMaxDynamicSharedMemorySize, SMEM_TOTAL);
    nlm_hmma_kernel<<<400, 512, SMEM_TOTAL>>>(img, out);
}

// round 6
// speedup vs baseline: 6.2084x; 1.4998x over previous
#include <cuda_runtime.h>
#include <cuda_fp16.h>
#include <stdint.h>
#include <math.h>

#define IMG   320
#define NPIX  1024
#define YROWB 144           // 72 halfs; stride%128=16 -> conflict-free ldmatrix

// shared layout (bytes): red overlays timg (timg dead after build)
#define SM_TIMG 0           // 12288 B (red: float4[512]=8KB after sync)
#define SM_AUX2 12288       // u32[4096]: per col-pair {I0e,I0o,I1e,I1o,I2e,I2o,sq'e,sq'o}
#define SM_Y    28672       // half[1024][72]
#define SMEM_TOTAL (28672 + NPIX * YROWB)   // 176128

#define LOG2E2  2.0813689810056077f     // (log2 e)^2
#define NEG2L2 (-4.1627379620112153f)   // -2*(log2 e)^2

typedef unsigned long long ull;

__device__ __forceinline__ uint32_t smem_u32(const void* p) {
    uint32_t a;
    asm("{ .reg .u64 t; cvta.to.shared.u64 t, %1; cvt.u32.u64 %0, t; }" : "=r"(a) : "l"(p));
    return a;
}
__device__ __forceinline__ ull fma2(ull a, ull b, ull c) {
    ull d; asm("fma.rn.f32x2 %0, %1, %2, %3;" : "=l"(d) : "l"(a), "l"(b), "l"(c));
    return d;
}
__device__ __forceinline__ ull add2(ull a, ull b) {
    ull d; asm("add.rn.f32x2 %0, %1, %2;" : "=l"(d) : "l"(a), "l"(b));
    return d;
}
__device__ __forceinline__ ull pack2(float lo, float hi) {
    ull d; asm("mov.b64 %0, {%1, %2};" : "=l"(d) : "f"(lo), "f"(hi));
    return d;
}
__device__ __forceinline__ float2 unpack2(ull v) {
    float lo, hi; asm("mov.b64 {%0, %1}, %2;" : "=f"(lo), "=f"(hi) : "l"(v));
    return make_float2(lo, hi);
}
__device__ __forceinline__ float sqrta(float x) {
    float y; asm("sqrt.approx.f32 %0, %1;" : "=f"(y) : "f"(x)); return y;
}
__device__ __forceinline__ float ex2a(float x) {
    float y; asm("ex2.approx.f32 %0, %1;" : "=f"(y) : "f"(x)); return y;
}

#define LDSM4(r, addr) \
    asm volatile("ldmatrix.sync.aligned.m8n8.x4.shared.b16 {%0,%1,%2,%3}, [%4];" \
        : "=r"((r)[0]), "=r"((r)[1]), "=r"((r)[2]), "=r"((r)[3]) : "r"(addr))
#define LDSM2(r, addr) \
    asm volatile("ldmatrix.sync.aligned.m8n8.x2.shared.b16 {%0,%1}, [%2];" \
        : "=r"((r)[0]), "=r"((r)[1]) : "r"(addr))
#define MMA16816(c, a, b0, b1) \
    asm volatile("mma.sync.aligned.m16n8k16.row.col.f32.f16.f16.f32 " \
        "{%0,%1,%2,%3}, {%4,%5,%6,%7}, {%8,%9}, {%0,%1,%2,%3};" \
        : "+f"((c)[0]), "+f"((c)[1]), "+f"((c)[2]), "+f"((c)[3]) \
        : "r"((a)[0]), "r"((a)[1]), "r"((a)[2]), "r"((a)[3]), "r"(b0), "r"(b1))
#define MMA16808(c, a, b0) \
    asm volatile("mma.sync.aligned.m16n8k8.row.col.f32.f16.f16.f32 " \
        "{%0,%1,%2,%3}, {%4,%5}, {%6}, {%0,%1,%2,%3};" \
        : "+f"((c)[0]), "+f"((c)[1]), "+f"((c)[2]), "+f"((c)[3]) \
        : "r"((a)[0]), "r"((a)[1]), "r"(b0))

__global__ __launch_bounds__(512, 1)
void nlm_hmma_kernel(const float* __restrict__ img, float* __restrict__ out)
{
    extern __shared__ char sm[];
    float*    timg  = (float*)(sm + SM_TIMG);
    float4*   red   = (float4*)(sm + SM_TIMG);     // overlays timg after build
    uint32_t* aux2u = (uint32_t*)(sm + SM_AUX2);
    char*     Yb    = sm + SM_Y;

    const int bid  = blockIdx.x;
    const int tile = bid >> 2, nb = bid & 3;       // 256 rows per CTA
    const int ti = tile / 10, tj = tile % 10;
    const int tid = threadIdx.x;
    const int gb = ti * 32 * IMG + tj * 32;

    // ---- tile image -> smem ----
    for (int i = tid; i < 3 * NPIX; i += 512) {
        int ch = i >> 10, pix = i & 1023;
        timg[i] = img[ch * (IMG * IMG) + gb + (pix >> 5) * IMG + (pix & 31)];
    }
    __syncthreads();

    // ---- build fp16 features Y[1024][72] + pair-interleaved aux ----
    for (int p = tid; p < NPIX; p += 512) {
        int r = p >> 5, c = p & 31;
        __half hl[72];
        float sq = 0.f;
        #pragma unroll
        for (int k = 0; k < 25; k++) {
            if (k == 12) continue;
            int kk = (k < 12) ? k : k - 1;
            int rr = min(max(r + k / 5 - 2, 0), 31);
            int cc = min(max(c + k % 5 - 2, 0), 31);
            int off = rr * 32 + cc;
            #pragma unroll
            for (int ch = 0; ch < 3; ch++) {
                float x = timg[ch * NPIX + off];
                __half h = __float2half_rn(x);
                float xr = __half2float(h);
                sq = fmaf(xr, xr, sq);
                hl[ch * 24 + kk] = h;
            }
        }
        __half2* yrow = (__half2*)(Yb + p * YROWB);
        #pragma unroll
        for (int i = 0; i < 36; i++)
            yrow[i] = __halves2half2(hl[2 * i], hl[2 * i + 1]);
        int ab = (p >> 1) * 8 + (p & 1);
        aux2u[ab + 0] = __float_as_uint(timg[p]);
        aux2u[ab + 2] = __float_as_uint(timg[NPIX + p]);
        aux2u[ab + 4] = __float_as_uint(timg[2 * NPIX + p]);
        aux2u[ab + 6] = __float_as_uint(sq * LOG2E2);       // pre-scaled norm
    }
    __syncthreads();

    // ---- warp geometry: 16 warps = 8 n-subblocks x 2 m-halves ----
    const int wid = tid >> 5, lane = tid & 31;
    const int wn = wid >> 1;
    const int wm2 = wid & 1;
    const int grb = nb * 256 + wn * 32;
    const uint32_t ybase = smem_u32(Yb);

    // ---- A fragments hoisted ----
    uint32_t a[2][4][4], a8[2][2];
    {
        int row = lane & 15;
        int cb  = (lane >> 4) << 4;
        #pragma unroll
        for (int nt = 0; nt < 2; nt++) {
            #pragma unroll
            for (int ks = 0; ks < 4; ks++)
                LDSM4(a[nt][ks], ybase + (uint32_t)(grb + nt * 16 + row) * YROWB + ks * 32 + cb);
            LDSM2(a8[nt], ybase + (uint32_t)(grb + nt * 16 + row) * YROWB + 128);
        }
    }

    // packed scaled row norms (splat)
    ull s2[2][2];
    #pragma unroll
    for (int nt = 0; nt < 2; nt++)
        #pragma unroll
        for (int h = 0; h < 2; h++) {
            int gr = grb + nt * 16 + h * 8 + (lane >> 2);
            float s = __uint_as_float(aux2u[(gr >> 1) * 8 + 6 + (gr & 1)]);
            s2[nt][h] = pack2(s, s);
        }

    const ull neg2 = pack2(NEG2L2, NEG2L2);
    ull den2[2][2] = {{0ull,0ull},{0ull,0ull}};
    ull rr0[2][2]  = {{0ull,0ull},{0ull,0ull}};
    ull rr1[2][2]  = {{0ull,0ull},{0ull,0ull}};
    ull rr2[2][2]  = {{0ull,0ull},{0ull,0ull}};

    // ---- stream m: 8 blocks of 128; warp's 64-col half in 2 groups of 32 ----
    for (int mb = 0; mb < 8; mb++) {
        #pragma unroll
        for (int g = 0; g < 2; g++) {
            const int mgb = mb * 128 + wm2 * 64 + g * 32;
            float c[2][4][4];
            #pragma unroll
            for (int nt = 0; nt < 2; nt++)
                #pragma unroll
                for (int mt = 0; mt < 4; mt++)
                    c[nt][mt][0] = c[nt][mt][1] = c[nt][mt][2] = c[nt][mt][3] = 0.f;

            #pragma unroll
            for (int ks = 0; ks < 4; ks++) {
                uint32_t b[8];
                #pragma unroll
                for (int bt = 0; bt < 2; bt++) {
                    int row = mgb + bt * 16 + (lane & 7) + ((lane >> 4) << 3);
                    int cb  = ks * 32 + (((lane >> 3) & 1) << 4);
                    LDSM4(&b[bt * 4], ybase + (uint32_t)row * YROWB + cb);
                }
                #pragma unroll
                for (int nt = 0; nt < 2; nt++)
                    #pragma unroll
                    for (int mt = 0; mt < 4; mt++) {
                        int bi = (mt >> 1) * 4 + (mt & 1) * 2;
                        MMA16816(c[nt][mt], a[nt][ks], b[bi], b[bi + 1]);
                    }
            }
            {   // k8 tail (cols 64..71)
                uint32_t b8[4];
                int row = mgb + (lane >> 3) * 8 + (lane & 7);
                LDSM4(b8, ybase + (uint32_t)row * YROWB + 128);
                #pragma unroll
                for (int nt = 0; nt < 2; nt++)
                    #pragma unroll
                    for (int mt = 0; mt < 4; mt++)
                        MMA16808(c[nt][mt], a8[nt], b8[mt]);
            }

            // ---- packed epilogue on this 32-col group ----
            const bool dg = (mgb == grb);           // warp-uniform diag block
            #pragma unroll
            for (int mt = 0; mt < 4; mt++) {
                const int c0 = mgb + mt * 8 + ((lane & 3) << 1);
                const ulonglong2* ap = (const ulonglong2*)(aux2u + (c0 >> 1) * 8);
                ulonglong2 v01 = ap[0];             // (I0 pair, I1 pair)
                ulonglong2 v23 = ap[1];             // (I2 pair, sq' pair)
                #pragma unroll
                for (int nt = 0; nt < 2; nt++)
                    #pragma unroll
                    for (int h = 0; h < 2; h++) {
                        ull c2  = pack2(c[nt][mt][h * 2], c[nt][mt][h * 2 + 1]);
                        ull dd2 = fma2(c2, neg2, add2(s2[nt][h], v23.y));
                        float2 dd = unpack2(dd2);
                        float w0 = ex2a(-sqrta(fmaxf(dd.x, 0.f)));
                        float w1 = ex2a(-sqrta(fmaxf(dd.y, 0.f)));
                        if (dg) {
                            int gr = grb + nt * 16 + h * 8 + (lane >> 2);
                            if (gr == c0)     w0 = 0.f;
                            if (gr == c0 + 1) w1 = 0.f;
                        }
                        ull w2 = pack2(w0, w1);
                        den2[nt][h] = add2(den2[nt][h], w2);
                        rr0[nt][h] = fma2(w2, v01.x, rr0[nt][h]);
                        rr1[nt][h] = fma2(w2, v01.y, rr1[nt][h]);
                        rr2[nt][h] = fma2(w2, v23.x, rr2[nt][h]);
                    }
            }
        }
    }

    __syncthreads();   // timg dead before red overlay

    // ---- horizontal combine + quad reduce + cross-half via smem ----
    #pragma unroll
    for (int nt = 0; nt < 2; nt++)
        #pragma unroll
        for (int h = 0; h < 2; h++) {
            float2 fd = unpack2(den2[nt][h]);
            float2 f0 = unpack2(rr0[nt][h]);
            float2 f1 = unpack2(rr1[nt][h]);
            float2 f2 = unpack2(rr2[nt][h]);
            float d = fd.x + fd.y, x = f0.x + f0.y, y = f1.x + f1.y, z = f2.x + f2.y;
            #pragma unroll
            for (int off = 1; off <= 2; off <<= 1) {
                d += __shfl_xor_sync(0xFFFFFFFFu, d, off);
                x += __shfl_xor_sync(0xFFFFFFFFu, x, off);
                y += __shfl_xor_sync(0xFFFFFFFFu, y, off);
                z += __shfl_xor_sync(0xFFFFFFFFu, z, off);
            }
            if ((lane & 3) == 0) {
                int rl = wn * 32 + nt * 16 + h * 8 + (lane >> 2);
                red[wm2 * 256 + rl] = make_float4(x, y, z, d);
            }
        }
    __syncthreads();

    if (tid < 256) {
        float4 p0 = red[tid], p1 = red[256 + tid];
        float inv = 1.f / (p0.w + p1.w);
        int n = nb * 256 + tid;
        int gp = gb + (n >> 5) * IMG + (n & 31);
        out[gp]                 = (p0.x + p1.x) * inv;
        out[IMG * IMG + gp]     = (p0.y + p1.y) * inv;
        out[2 * IMG * IMG + gp] = (p0.z + p1.z) * inv;
    }
}

extern "C" void kernel_launch(void* const* d_in, const int* in_sizes, int n_in,
                              void* d_out, int out_size)
{
    (void)in_sizes; (void)n_in; (void)out_size;
    const float* img = (const float*)d_in[0];
    float* out = (float*)d_out;
    cudaFuncSetAttribute(nlm_hmma_kernel, cudaFuncAttributeMaxDynamicSharedMemorySize, SMEM_TOTAL);
    nlm_hmma_kernel<<<400, 512, SMEM_TOTAL>>>(img, out);
}